// round 13
// baseline (speedup 1.0000x reference)
#include <cuda_runtime.h>
#include <math.h>
#include <stdint.h>

#define D_MODEL 1024
#define NHEADS  16
#define DKH     64
#define BATCH   4
#define SEQ     2048
#define MT      (BATCH*SEQ)   // 8192 rows

// ---------------- scratch (device globals; no cudaMalloc allowed) ----------
__device__ float g_q[(size_t)MT * D_MODEL];
__device__ float g_k[(size_t)MT * D_MODEL];
__device__ float g_v[(size_t)MT * D_MODEL];
__device__ float g_ctx[(size_t)MT * D_MODEL];
__device__ float g_xc[(size_t)MT * D_MODEL];              // tf32+permuted A operand
__device__ float g_wc[(size_t)4 * D_MODEL * D_MODEL];     // tf32+permuted weights
__device__ float2 g_rope[(size_t)SEQ * 32];               // [s][k] -> (cos, sin)

// ---------------- helpers ---------------------------------------------------
__device__ __forceinline__ uint32_t f2tf(float x) {
    uint32_t r;
    asm("cvt.rna.tf32.f32 %0, %1;" : "=r"(r) : "f"(x));
    return r;
}
__device__ __forceinline__ float tfv(float x) { return __uint_as_float(f2tf(x)); }

__device__ __forceinline__ void mma_tf32_p(
    float* c,
    uint32_t a0, uint32_t a1, uint32_t a2, uint32_t a3,
    uint32_t b0, uint32_t b1)
{
    asm volatile(
        "mma.sync.aligned.m16n8k8.row.col.f32.tf32.tf32.f32 "
        "{%0,%1,%2,%3},{%4,%5,%6,%7},{%8,%9},{%0,%1,%2,%3};"
        : "+f"(c[0]), "+f"(c[1]), "+f"(c[2]), "+f"(c[3])
        : "r"(a0), "r"(a1), "r"(a2), "r"(a3), "r"(b0), "r"(b1));
}

__device__ __forceinline__ int swz(int r) { return (r & 3) ^ ((r >> 2) & 3); }

__device__ __forceinline__ void cpa16(uint32_t saddr, const float* g) {
    asm volatile("cp.async.ca.shared.global [%0], [%1], 16;" :: "r"(saddr), "l"(g));
}
#define CPA_COMMIT() asm volatile("cp.async.commit_group;")
#define CPA_WAIT2()  asm volatile("cp.async.wait_group 2;")

// ---------------- tf32 convert + fragment-permute ---------------------------
// Per 16-element k-panel: out[4*(k&3)+(k>>2)] = tf32(in[k]).
// A contiguous 16B quad of 'out' is then one mma fragment quad {c,c+4,c+8,c+12}.
__device__ __forceinline__ void tfperm_group(const float* in, float* out)
{
    const float4* p = (const float4*)in;
    float4 v0 = p[0], v1 = p[1], v2 = p[2], v3 = p[3];
    float a[16] = {v0.x, v0.y, v0.z, v0.w, v1.x, v1.y, v1.z, v1.w,
                   v2.x, v2.y, v2.z, v2.w, v3.x, v3.y, v3.z, v3.w};
    float4* q = (float4*)out;
    q[0] = make_float4(tfv(a[0]), tfv(a[4]), tfv(a[8]),  tfv(a[12]));
    q[1] = make_float4(tfv(a[1]), tfv(a[5]), tfv(a[9]),  tfv(a[13]));
    q[2] = make_float4(tfv(a[2]), tfv(a[6]), tfv(a[10]), tfv(a[14]));
    q[3] = make_float4(tfv(a[3]), tfv(a[7]), tfv(a[11]), tfv(a[15]));
}

__global__ void tfperm_kernel(const float* __restrict__ in, float* __restrict__ out, int n16)
{
    int i = blockIdx.x * 256 + threadIdx.x;
    if (i >= n16) return;
    tfperm_group(in + (size_t)i * 16, out + (size_t)i * 16);
}

__global__ void tfperm_w_kernel(const float* __restrict__ w0, const float* __restrict__ w1,
                                const float* __restrict__ w2, const float* __restrict__ w3,
                                float* __restrict__ outbase)
{
    int i = blockIdx.x * 256 + threadIdx.x;   // 65536 groups of 16
    const float* in = (blockIdx.y == 0) ? w0 : (blockIdx.y == 1) ? w1
                     : (blockIdx.y == 2) ? w2 : w3;
    float* out = outbase + (size_t)blockIdx.y * D_MODEL * D_MODEL;
    tfperm_group(in + (size_t)i * 16, out + (size_t)i * 16);
}

// ---------------- RoPE cos/sin table ----------------------------------------
__global__ void rope_table_kernel(const int* __restrict__ pos32)
{
    int idx = blockIdx.x * 256 + threadIdx.x;
    if (idx >= SEQ * 32) return;
    int s = idx >> 5;
    int k = idx & 31;
    const bool is64 = (pos32[1] == 0 && pos32[2] == 1);
    long long pv = is64 ? ((const long long*)pos32)[s] : (long long)pos32[s];
    float p   = (float)pv;
    float inv = powf(10000.0f, -(float)k * (1.0f / 32.0f));
    float sn, cs;
    sincosf(p * inv, &sn, &cs);
    g_rope[idx] = make_float2(cs, sn);
}

// ---------------- RoPE apply (table-based, float4 = 2 pairs / thread) -------
__global__ void rope_apply_kernel()
{
    const size_t QUADS = (size_t)MT * (D_MODEL / 4);
    size_t idx = (size_t)blockIdx.x * blockDim.x + threadIdx.x;
    if (idx >= QUADS) return;
    float* X = (blockIdx.y == 0) ? g_q : g_k;

    const int m = (int)(idx >> 8);
    const int c4 = (int)(idx & 255);
    const int col = c4 * 4;
    const int k0 = (col & 63) >> 1;
    const int s  = m & (SEQ - 1);

    float2 cs0 = g_rope[s * 32 + k0];
    float2 cs1 = g_rope[s * 32 + k0 + 1];

    float4 v = *(float4*)(X + (size_t)m * D_MODEL + col);
    float4 r;
    r.x = cs0.x * v.x - cs0.y * v.y;
    r.y = cs0.y * v.x + cs0.x * v.y;
    r.z = cs1.x * v.z - cs1.y * v.w;
    r.w = cs1.y * v.z + cs1.x * v.w;
    *(float4*)(X + (size_t)m * D_MODEL + col) = r;
}

// ---------------- tf32 GEMM via cp.async, pre-converted inputs --------------
// C[m,n] = sum_d A[m,d] * W[n,d]; A and W are tf32-rounded + fragment-permuted.
// 128x128 tile, BK=16, 4-stage cp.async pipeline, 8 warps (4m x 2n).
// smem: A stages [4][2048]w then W stages [4][2048]w (dynamic, 64KB).
#define GEMM_SMEM_B (4 * 2048 * 2 * 4)

__global__ __launch_bounds__(256, 2) void gemm_tf32_kernel(
    const float* __restrict__ Ac,
    const float* __restrict__ Wbase, size_t wstep,
    float* __restrict__ C0, float* __restrict__ C1, float* __restrict__ C2)
{
    extern __shared__ uint32_t smu[];
    const float* Wc = Wbase + (size_t)blockIdx.z * wstep;
    float* C = (blockIdx.z == 0) ? C0 : (blockIdx.z == 1) ? C1 : C2;

    const int tid = threadIdx.x;
    const int w  = tid >> 5;
    const int l  = tid & 31;
    const int g  = l >> 2;
    const int tg = l & 3;
    const int m0 = blockIdx.y * 128;
    const int n0 = blockIdx.x * 128;
    const int wm = (w & 3) * 32;
    const int wn = (w >> 2) * 64;

    // loader mapping: 2 threads per row, each copies 2x16B quads
    const int lr  = tid >> 1;         // 0..127
    const int lcq = (tid & 1) * 2;    // quad base: 0 or 2
    const int srx = swz(lr);
    const float* Agc = Ac + (size_t)(m0 + lr) * D_MODEL + lcq * 4;
    const float* Wgc = Wc + (size_t)(n0 + lr) * D_MODEL + lcq * 4;

    uint32_t sm0 = (uint32_t)__cvta_generic_to_shared(smu);
    const uint32_t aA = sm0 + (uint32_t)(lr * 16) * 4;
    const uint32_t aW = sm0 + (uint32_t)(4 * 2048 + lr * 16) * 4;
    const uint32_t b0 = 16u * (uint32_t)(lcq ^ srx);
    const uint32_t b1 = 16u * (uint32_t)((lcq + 1) ^ srx);

    // fragment word offsets within a stage
    int aoff[2][2], boff[8];
#pragma unroll
    for (int mi = 0; mi < 2; mi++)
#pragma unroll
        for (int hf = 0; hf < 2; hf++) {
            int row = wm + 16 * mi + 8 * hf + g;
            aoff[mi][hf] = row * 16 + 4 * (tg ^ swz(row));
        }
#pragma unroll
    for (int ni = 0; ni < 8; ni++) {
        int row = wn + 8 * ni + g;
        boff[ni] = row * 16 + 4 * (tg ^ swz(row));
    }

    float acc[2][8][4];
#pragma unroll
    for (int mi = 0; mi < 2; mi++)
#pragma unroll
        for (int ni = 0; ni < 8; ni++)
#pragma unroll
            for (int j = 0; j < 4; j++) acc[mi][ni][j] = 0.0f;

    // prologue: stages 0..2 for t = 0..2
#pragma unroll
    for (int s = 0; s < 3; s++) {
        const float* ga = Agc + s * 16;
        const float* gw = Wgc + s * 16;
        cpa16(aA + s * 8192 + b0, ga);
        cpa16(aA + s * 8192 + b1, ga + 4);
        cpa16(aW + s * 8192 + b0, gw);
        cpa16(aW + s * 8192 + b1, gw + 4);
        CPA_COMMIT();
    }

#pragma unroll 1
    for (int t = 0; t < D_MODEL / 16; t++) {
        CPA_WAIT2();           // stage t complete (<=2 younger groups pending)
        __syncthreads();       // visible to all warps; stage t-1 fully consumed

        if (t < D_MODEL / 16 - 3) {
            const int s = (t + 3) & 3;
            const float* ga = Agc + (t + 3) * 16;
            const float* gw = Wgc + (t + 3) * 16;
            cpa16(aA + s * 8192 + b0, ga);
            cpa16(aA + s * 8192 + b1, ga + 4);
            cpa16(aW + s * 8192 + b0, gw);
            cpa16(aW + s * 8192 + b1, gw + 4);
        }
        CPA_COMMIT();          // unconditional: keeps group accounting constant

        const uint32_t* Ab = smu + (t & 3) * 2048;
        const uint32_t* Wb = smu + 4 * 2048 + (t & 3) * 2048;
        uint4 af[2][2], bf[8];
#pragma unroll
        for (int mi = 0; mi < 2; mi++) {
            af[mi][0] = *(const uint4*)&Ab[aoff[mi][0]];
            af[mi][1] = *(const uint4*)&Ab[aoff[mi][1]];
        }
#pragma unroll
        for (int ni = 0; ni < 8; ni++)
            bf[ni] = *(const uint4*)&Wb[boff[ni]];

#pragma unroll
        for (int mi = 0; mi < 2; mi++)
#pragma unroll
            for (int ni = 0; ni < 8; ni++) {
                mma_tf32_p(acc[mi][ni],
                           af[mi][0].x, af[mi][1].x, af[mi][0].y, af[mi][1].y,
                           bf[ni].x, bf[ni].y);
                mma_tf32_p(acc[mi][ni],
                           af[mi][0].z, af[mi][1].z, af[mi][0].w, af[mi][1].w,
                           bf[ni].z, bf[ni].w);
            }
    }

#pragma unroll
    for (int mi = 0; mi < 2; mi++) {
        const size_t row0 = (size_t)(m0 + wm + 16 * mi + g);
        const size_t row1 = row0 + 8;
#pragma unroll
        for (int ni = 0; ni < 8; ni++) {
            const int col = n0 + wn + 8 * ni + 2 * tg;
            *(float2*)(C + row0 * D_MODEL + col) = make_float2(acc[mi][ni][0], acc[mi][ni][1]);
            *(float2*)(C + row1 * D_MODEL + col) = make_float2(acc[mi][ni][2], acc[mi][ni][3]);
        }
    }
}

// ---------------- tf32 tensor-core flash attention (unchanged, passing) -----
#define KS_STRIDE 68
#define VS_STRIDE 72
#define PS_STRIDE 68
#define ATTN_SMEM_W (64*KS_STRIDE + 64*VS_STRIDE + 64*PS_STRIDE)
#define ATTN_SMEM_B (ATTN_SMEM_W * 4)

__device__ __forceinline__ void mma_tf32(
    float& c0, float& c1, float& c2, float& c3,
    uint32_t a0, uint32_t a1, uint32_t a2, uint32_t a3,
    uint32_t b0, uint32_t b1)
{
    asm volatile(
        "mma.sync.aligned.m16n8k8.row.col.f32.tf32.tf32.f32 "
        "{%0,%1,%2,%3},{%4,%5,%6,%7},{%8,%9},{%0,%1,%2,%3};"
        : "+f"(c0), "+f"(c1), "+f"(c2), "+f"(c3)
        : "r"(a0), "r"(a1), "r"(a2), "r"(a3), "r"(b0), "r"(b1));
}

__global__ __launch_bounds__(128) void attn_tf32_kernel()
{
    extern __shared__ uint32_t smu[];
    uint32_t* Ks = smu;
    uint32_t* Vs = smu + 64 * KS_STRIDE;
    uint32_t* Ps = smu + 64 * KS_STRIDE + 64 * VS_STRIDE;

    const int qb = blockIdx.x, h = blockIdx.y, b = blockIdx.z;
    const int q0 = qb * 64;
    const int tid = threadIdx.x;
    const int w  = tid >> 5;
    const int l  = tid & 31;
    const int g  = l >> 2;
    const int tg = l & 3;

    const float* Qg = g_q + ((size_t)(b * SEQ + q0)) * D_MODEL + h * DKH;
    const float* Kg = g_k + ((size_t)b * SEQ) * D_MODEL + h * DKH;
    const float* Vg = g_v + ((size_t)b * SEQ) * D_MODEL + h * DKH;

    uint32_t qa[8][4];
    {
        const float* r0 = Qg + (size_t)(16 * w + g) * D_MODEL;
        const float* r1 = Qg + (size_t)(16 * w + g + 8) * D_MODEL;
#pragma unroll
        for (int kc = 0; kc < 8; kc++) {
            qa[kc][0] = f2tf(r0[8 * kc + tg]);
            qa[kc][1] = f2tf(r1[8 * kc + tg]);
            qa[kc][2] = f2tf(r0[8 * kc + tg + 4]);
            qa[kc][3] = f2tf(r1[8 * kc + tg + 4]);
        }
    }

    float o[8][4];
#pragma unroll
    for (int dc = 0; dc < 8; dc++)
#pragma unroll
        for (int j = 0; j < 4; j++) o[dc][j] = 0.0f;
    float m0 = -1e30f, m1 = -1e30f, l0 = 0.0f, l1 = 0.0f;

    for (int kb = 0; kb <= qb; kb++) {
        const int k0 = kb * 64;
        __syncthreads();
#pragma unroll
        for (int i = 0; i < 8; i++) {
            int idx = tid + 128 * i;
            int r   = idx >> 4;
            int c   = (idx & 15) * 4;
            float4 kv = *(const float4*)(Kg + (size_t)(k0 + r) * D_MODEL + c);
            float4 vv = *(const float4*)(Vg + (size_t)(k0 + r) * D_MODEL + c);
            uint4 kt = make_uint4(f2tf(kv.x), f2tf(kv.y), f2tf(kv.z), f2tf(kv.w));
            uint4 vt = make_uint4(f2tf(vv.x), f2tf(vv.y), f2tf(vv.z), f2tf(vv.w));
            *(uint4*)&Ks[r * KS_STRIDE + c] = kt;
            *(uint4*)&Vs[r * VS_STRIDE + c] = vt;
        }
        __syncthreads();

        float s[8][4];
#pragma unroll
        for (int nc = 0; nc < 8; nc++)
#pragma unroll
            for (int j = 0; j < 4; j++) s[nc][j] = 0.0f;

#pragma unroll
        for (int nc = 0; nc < 8; nc++) {
            const uint32_t* krow = &Ks[(8 * nc + g) * KS_STRIDE];
#pragma unroll
            for (int kc = 0; kc < 8; kc++) {
                uint32_t b0 = krow[8 * kc + tg];
                uint32_t b1 = krow[8 * kc + tg + 4];
                mma_tf32(s[nc][0], s[nc][1], s[nc][2], s[nc][3],
                         qa[kc][0], qa[kc][1], qa[kc][2], qa[kc][3], b0, b1);
            }
        }

#pragma unroll
        for (int nc = 0; nc < 8; nc++)
#pragma unroll
            for (int j = 0; j < 4; j++) s[nc][j] *= 0.125f;

        if (kb == qb) {
            const int r0 = 16 * w + g, r1 = r0 + 8;
#pragma unroll
            for (int nc = 0; nc < 8; nc++) {
                int c0 = 8 * nc + 2 * tg, c1 = c0 + 1;
                if (c0 > r0) s[nc][0] = -1e30f;
                if (c1 > r0) s[nc][1] = -1e30f;
                if (c0 > r1) s[nc][2] = -1e30f;
                if (c1 > r1) s[nc][3] = -1e30f;
            }
        }

        float rm0 = -1e30f, rm1 = -1e30f;
#pragma unroll
        for (int nc = 0; nc < 8; nc++) {
            rm0 = fmaxf(rm0, fmaxf(s[nc][0], s[nc][1]));
            rm1 = fmaxf(rm1, fmaxf(s[nc][2], s[nc][3]));
        }
        rm0 = fmaxf(rm0, __shfl_xor_sync(0xffffffffu, rm0, 1));
        rm0 = fmaxf(rm0, __shfl_xor_sync(0xffffffffu, rm0, 2));
        rm1 = fmaxf(rm1, __shfl_xor_sync(0xffffffffu, rm1, 1));
        rm1 = fmaxf(rm1, __shfl_xor_sync(0xffffffffu, rm1, 2));

        float mn0 = fmaxf(m0, rm0), mn1 = fmaxf(m1, rm1);
        float al0 = __expf(m0 - mn0), al1 = __expf(m1 - mn1);
        m0 = mn0; m1 = mn1;

        float rs0 = 0.0f, rs1 = 0.0f;
#pragma unroll
        for (int nc = 0; nc < 8; nc++) {
            float p0 = __expf(s[nc][0] - mn0);
            float p1 = __expf(s[nc][1] - mn0);
            float p2 = __expf(s[nc][2] - mn1);
            float p3 = __expf(s[nc][3] - mn1);
            s[nc][0] = p0; s[nc][1] = p1; s[nc][2] = p2; s[nc][3] = p3;
            rs0 += p0 + p1; rs1 += p2 + p3;
        }
        rs0 += __shfl_xor_sync(0xffffffffu, rs0, 1);
        rs0 += __shfl_xor_sync(0xffffffffu, rs0, 2);
        rs1 += __shfl_xor_sync(0xffffffffu, rs1, 1);
        rs1 += __shfl_xor_sync(0xffffffffu, rs1, 2);
        l0 = l0 * al0 + rs0;
        l1 = l1 * al1 + rs1;

#pragma unroll
        for (int dc = 0; dc < 8; dc++) {
            o[dc][0] *= al0; o[dc][1] *= al0;
            o[dc][2] *= al1; o[dc][3] *= al1;
        }

        {
            const int r0 = 16 * w + g, r1 = r0 + 8;
#pragma unroll
            for (int nc = 0; nc < 8; nc++) {
                uint2 p01 = make_uint2(f2tf(s[nc][0]), f2tf(s[nc][1]));
                uint2 p23 = make_uint2(f2tf(s[nc][2]), f2tf(s[nc][3]));
                *(uint2*)&Ps[r0 * PS_STRIDE + 8 * nc + 2 * tg] = p01;
                *(uint2*)&Ps[r1 * PS_STRIDE + 8 * nc + 2 * tg] = p23;
            }
        }
        __syncwarp();

        uint32_t pa[8][4];
        {
            const uint32_t* p0 = &Ps[(16 * w + g) * PS_STRIDE];
            const uint32_t* p1 = &Ps[(16 * w + g + 8) * PS_STRIDE];
#pragma unroll
            for (int nc = 0; nc < 8; nc++) {
                pa[nc][0] = p0[8 * nc + tg];
                pa[nc][1] = p1[8 * nc + tg];
                pa[nc][2] = p0[8 * nc + tg + 4];
                pa[nc][3] = p1[8 * nc + tg + 4];
            }
        }

#pragma unroll
        for (int dc = 0; dc < 8; dc++) {
#pragma unroll
            for (int nc = 0; nc < 8; nc++) {
                uint32_t b0 = Vs[(8 * nc + tg) * VS_STRIDE + 8 * dc + g];
                uint32_t b1 = Vs[(8 * nc + tg + 4) * VS_STRIDE + 8 * dc + g];
                mma_tf32(o[dc][0], o[dc][1], o[dc][2], o[dc][3],
                         pa[nc][0], pa[nc][1], pa[nc][2], pa[nc][3], b0, b1);
            }
        }
    }

    float* Og = g_ctx + ((size_t)(b * SEQ + q0)) * D_MODEL + h * DKH;
    float il0 = 1.0f / l0, il1 = 1.0f / l1;
    float* w0 = Og + (size_t)(16 * w + g) * D_MODEL;
    float* w1 = Og + (size_t)(16 * w + g + 8) * D_MODEL;
#pragma unroll
    for (int dc = 0; dc < 8; dc++) {
        *(float2*)(w0 + 8 * dc + 2 * tg) = make_float2(o[dc][0] * il0, o[dc][1] * il0);
        *(float2*)(w1 + 8 * dc + 2 * tg) = make_float2(o[dc][2] * il1, o[dc][3] * il1);
    }
}

// ---------------- launch ---------------------------------------------------
extern "C" void kernel_launch(void* const* d_in, const int* in_sizes, int n_in,
                              void* d_out, int out_size)
{
    const float*      X   = (const float*)d_in[0];
    const int*        pos = (const int*)d_in[1];
    const float*      Wq  = (const float*)d_in[2];
    const float*      Wk  = (const float*)d_in[3];
    const float*      Wv  = (const float*)d_in[4];
    const float*      Wo  = (const float*)d_in[5];
    float*            out = (float*)d_out;

    float *dq, *dk, *dv, *dctx, *dxc, *dwc;
    cudaGetSymbolAddress((void**)&dq,   g_q);
    cudaGetSymbolAddress((void**)&dk,   g_k);
    cudaGetSymbolAddress((void**)&dv,   g_v);
    cudaGetSymbolAddress((void**)&dctx, g_ctx);
    cudaGetSymbolAddress((void**)&dxc,  g_xc);
    cudaGetSymbolAddress((void**)&dwc,  g_wc);

    cudaFuncSetAttribute(gemm_tf32_kernel, cudaFuncAttributeMaxDynamicSharedMemorySize, GEMM_SMEM_B);
    cudaFuncSetAttribute(attn_tf32_kernel, cudaFuncAttributeMaxDynamicSharedMemorySize, ATTN_SMEM_B);

    // RoPE table (transcendentals once)
    rope_table_kernel<<<(SEQ * 32 + 255) / 256, 256>>>(pos);

    // pre-convert: X and weights -> tf32 + fragment-permuted
    tfperm_kernel<<<(MT * D_MODEL / 16 + 255) / 256, 256>>>(X, dxc, MT * D_MODEL / 16);
    {
        dim3 gw(D_MODEL * D_MODEL / 16 / 256, 4);
        tfperm_w_kernel<<<gw, 256>>>(Wq, Wk, Wv, Wo, dwc);
    }

    // QKV projections
    dim3 gqkv(D_MODEL / 128, MT / 128, 3);
    gemm_tf32_kernel<<<gqkv, 256, GEMM_SMEM_B>>>(dxc, dwc, (size_t)D_MODEL * D_MODEL,
                                                 dq, dk, dv);

    // RoPE on Q and K
    dim3 gr((unsigned)(((size_t)MT * (D_MODEL / 4) + 255) / 256), 2, 1);
    rope_apply_kernel<<<gr, 256>>>();

    // causal attention
    dim3 ga(SEQ / 64, NHEADS, BATCH);
    attn_tf32_kernel<<<ga, 128, ATTN_SMEM_B>>>();

    // convert ctx, then output projection
    tfperm_kernel<<<(MT * D_MODEL / 16 + 255) / 256, 256>>>(dctx, dxc, MT * D_MODEL / 16);
    dim3 go(D_MODEL / 128, MT / 128, 1);
    gemm_tf32_kernel<<<go, 256, GEMM_SMEM_B>>>(dxc, dwc + (size_t)3 * D_MODEL * D_MODEL, 0,
                                               out, out, out);
}

// round 14
// speedup vs baseline: 1.4362x; 1.4362x over previous
#include <cuda_runtime.h>
#include <cuda_fp16.h>
#include <math.h>
#include <stdint.h>

#define D_MODEL 1024
#define NHEADS  16
#define DKH     64
#define BATCH   4
#define SEQ     2048
#define MT      (BATCH*SEQ)   // 8192 rows

// ---------------- scratch (device globals; no cudaMalloc allowed) ----------
__device__ float g_q[(size_t)MT * D_MODEL];
__device__ float g_k[(size_t)MT * D_MODEL];
__device__ float g_v[(size_t)MT * D_MODEL];
__device__ float g_ctx[(size_t)MT * D_MODEL];
__device__ float2 g_rope[(size_t)SEQ * 32];   // [s][k] -> (cos, sin)

// ---------------- helpers ---------------------------------------------------
__device__ __forceinline__ uint32_t f2tf(float x) {
    uint32_t r;
    asm("cvt.rna.tf32.f32 %0, %1;" : "=r"(r) : "f"(x));
    return r;
}

__device__ __forceinline__ int swz(int r) { return (r & 3) ^ ((r >> 2) & 3); }

__device__ __forceinline__ uint32_t packh2(float lo, float hi) {
    __half2 h = __floats2half2_rn(lo, hi);   // .x = lo bits[0:16)
    return *(uint32_t*)&h;
}

__device__ __forceinline__ void mma_f16(
    float* c, uint32_t a0, uint32_t a1, uint32_t a2, uint32_t a3,
    uint32_t b0, uint32_t b1)
{
    asm volatile(
        "mma.sync.aligned.m16n8k16.row.col.f32.f16.f16.f32 "
        "{%0,%1,%2,%3},{%4,%5,%6,%7},{%8,%9},{%0,%1,%2,%3};"
        : "+f"(c[0]), "+f"(c[1]), "+f"(c[2]), "+f"(c[3])
        : "r"(a0), "r"(a1), "r"(a2), "r"(a3), "r"(b0), "r"(b1));
}

// ---------------- RoPE cos/sin table ----------------------------------------
__global__ void rope_table_kernel(const int* __restrict__ pos32)
{
    int idx = blockIdx.x * 256 + threadIdx.x;
    if (idx >= SEQ * 32) return;
    int s = idx >> 5;
    int k = idx & 31;
    const bool is64 = (pos32[1] == 0 && pos32[2] == 1);
    long long pv = is64 ? ((const long long*)pos32)[s] : (long long)pos32[s];
    float p   = (float)pv;
    float inv = powf(10000.0f, -(float)k * (1.0f / 32.0f));
    float sn, cs;
    sincosf(p * inv, &sn, &cs);
    g_rope[idx] = make_float2(cs, sn);
}

// ---------------- RoPE apply (table-based, float4 = 2 pairs / thread) -------
__global__ void rope_apply_kernel()
{
    const size_t QUADS = (size_t)MT * (D_MODEL / 4);
    size_t idx = (size_t)blockIdx.x * blockDim.x + threadIdx.x;
    if (idx >= QUADS) return;
    float* X = (blockIdx.y == 0) ? g_q : g_k;

    const int m = (int)(idx >> 8);
    const int c4 = (int)(idx & 255);
    const int col = c4 * 4;
    const int k0 = (col & 63) >> 1;
    const int s  = m & (SEQ - 1);

    float2 cs0 = g_rope[s * 32 + k0];
    float2 cs1 = g_rope[s * 32 + k0 + 1];

    float4 v = *(float4*)(X + (size_t)m * D_MODEL + col);
    float4 r;
    r.x = cs0.x * v.x - cs0.y * v.y;
    r.y = cs0.y * v.x + cs0.x * v.y;
    r.z = cs1.x * v.z - cs1.y * v.w;
    r.w = cs1.y * v.z + cs1.x * v.w;
    *(float4*)(X + (size_t)m * D_MODEL + col) = r;
}

// ---------------- fp16 GEMM: C[m,n] = sum_d A[m,d] * W[n,d]  (NT) -----------
// 128x128 tile, BK=16, 256 thr = 8 warps (4m x 2n), warp tile 32x64.
// fp16 m16n8k16 mma (same 10-bit mantissa as tf32; fp32 accum).
// smem pair layout: word(r,p) = r*8 + 2*((p&3)^swz(r)) + (p>>2), p = k/2.
//   -> fragment (pair tg, pair tg+4) is one conflict-free LDS.64.
//   -> staging is 4 conflict-free STS.64 per row.
// Control flow identical to the proven R12 kernel (store/sync/prefetch/consume).
__global__ __launch_bounds__(256, 2) void gemm_f16_kernel(
    const float* __restrict__ A,
    const float* __restrict__ W0, const float* __restrict__ W1, const float* __restrict__ W2,
    float* __restrict__ C0, float* __restrict__ C1, float* __restrict__ C2)
{
    const float* W; float* C;
    if (blockIdx.z == 0)      { W = W0; C = C0; }
    else if (blockIdx.z == 1) { W = W1; C = C1; }
    else                      { W = W2; C = C2; }

    __shared__ uint32_t As[2][128 * 8];
    __shared__ uint32_t Ws[2][128 * 8];

    const int tid = threadIdx.x;
    const int w  = tid >> 5;
    const int l  = tid & 31;
    const int g  = l >> 2;
    const int tg = l & 3;
    const int m0 = blockIdx.y * 128;
    const int n0 = blockIdx.x * 128;
    const int wm = (w & 3) * 32;
    const int wn = (w >> 2) * 64;

    // loader: one thread per row; tid<128 -> A rows, tid>=128 -> W rows
    const int lr = tid & 127;
    const bool isA = (tid < 128);
    const float* G = isA ? (A + (size_t)(m0 + lr) * D_MODEL)
                         : (W + (size_t)(n0 + lr) * D_MODEL);
    const int srx = swz(lr);
    const int sq0 = 2 * (0 ^ srx), sq1 = 2 * (1 ^ srx);
    const int sq2 = 2 * (2 ^ srx), sq3 = 2 * (3 ^ srx);

    // fragment word offsets
    int aoff[2][2], boff[8];
#pragma unroll
    for (int mi = 0; mi < 2; mi++)
#pragma unroll
        for (int hf = 0; hf < 2; hf++) {
            int row = wm + 16 * mi + 8 * hf + g;
            aoff[mi][hf] = row * 8 + 2 * (tg ^ swz(row));
        }
#pragma unroll
    for (int ni = 0; ni < 8; ni++) {
        int row = wn + 8 * ni + g;
        boff[ni] = row * 8 + 2 * (tg ^ swz(row));
    }

    float acc[2][8][4];
#pragma unroll
    for (int mi = 0; mi < 2; mi++)
#pragma unroll
        for (int ni = 0; ni < 8; ni++)
#pragma unroll
            for (int j = 0; j < 4; j++) acc[mi][ni][j] = 0.0f;

    // prefetch first 16-float k-panel
    float4 v0 = *(const float4*)(G + 0);
    float4 v1 = *(const float4*)(G + 4);
    float4 v2 = *(const float4*)(G + 8);
    float4 v3 = *(const float4*)(G + 12);

#pragma unroll 1
    for (int t = 0; t < D_MODEL / 16; t++) {
        const int buf = t & 1;
        {
            uint32_t* Sb = (isA ? As[buf] : Ws[buf]) + lr * 8;
            // pk[p] = pack(k=2p, k=2p+1)
            uint32_t pk0 = packh2(v0.x, v0.y);
            uint32_t pk1 = packh2(v0.z, v0.w);
            uint32_t pk2 = packh2(v1.x, v1.y);
            uint32_t pk3 = packh2(v1.z, v1.w);
            uint32_t pk4 = packh2(v2.x, v2.y);
            uint32_t pk5 = packh2(v2.z, v2.w);
            uint32_t pk6 = packh2(v3.x, v3.y);
            uint32_t pk7 = packh2(v3.z, v3.w);
            *(uint2*)&Sb[sq0] = make_uint2(pk0, pk4);
            *(uint2*)&Sb[sq1] = make_uint2(pk1, pk5);
            *(uint2*)&Sb[sq2] = make_uint2(pk2, pk6);
            *(uint2*)&Sb[sq3] = make_uint2(pk3, pk7);
        }
        __syncthreads();

        if (t + 1 < D_MODEL / 16) {
            const float* Gn = G + (t + 1) * 16;
            v0 = *(const float4*)(Gn + 0);
            v1 = *(const float4*)(Gn + 4);
            v2 = *(const float4*)(Gn + 8);
            v3 = *(const float4*)(Gn + 12);
        }

        {
            const uint32_t* Ab = As[buf];
            const uint32_t* Wb = Ws[buf];
            uint2 af[2][2], bf[8];
#pragma unroll
            for (int mi = 0; mi < 2; mi++) {
                af[mi][0] = *(const uint2*)&Ab[aoff[mi][0]];
                af[mi][1] = *(const uint2*)&Ab[aoff[mi][1]];
            }
#pragma unroll
            for (int ni = 0; ni < 8; ni++)
                bf[ni] = *(const uint2*)&Wb[boff[ni]];

#pragma unroll
            for (int mi = 0; mi < 2; mi++)
#pragma unroll
                for (int ni = 0; ni < 8; ni++)
                    mma_f16(acc[mi][ni],
                            af[mi][0].x, af[mi][1].x, af[mi][0].y, af[mi][1].y,
                            bf[ni].x, bf[ni].y);
        }
    }

#pragma unroll
    for (int mi = 0; mi < 2; mi++) {
        const size_t row0 = (size_t)(m0 + wm + 16 * mi + g);
        const size_t row1 = row0 + 8;
#pragma unroll
        for (int ni = 0; ni < 8; ni++) {
            const int col = n0 + wn + 8 * ni + 2 * tg;
            *(float2*)(C + row0 * D_MODEL + col) = make_float2(acc[mi][ni][0], acc[mi][ni][1]);
            *(float2*)(C + row1 * D_MODEL + col) = make_float2(acc[mi][ni][2], acc[mi][ni][3]);
        }
    }
}

// ---------------- tf32 tensor-core flash attention (unchanged, passing) -----
#define KS_STRIDE 68
#define VS_STRIDE 72
#define PS_STRIDE 68
#define ATTN_SMEM_W (64*KS_STRIDE + 64*VS_STRIDE + 64*PS_STRIDE)
#define ATTN_SMEM_B (ATTN_SMEM_W * 4)

__device__ __forceinline__ void mma_tf32(
    float& c0, float& c1, float& c2, float& c3,
    uint32_t a0, uint32_t a1, uint32_t a2, uint32_t a3,
    uint32_t b0, uint32_t b1)
{
    asm volatile(
        "mma.sync.aligned.m16n8k8.row.col.f32.tf32.tf32.f32 "
        "{%0,%1,%2,%3},{%4,%5,%6,%7},{%8,%9},{%0,%1,%2,%3};"
        : "+f"(c0), "+f"(c1), "+f"(c2), "+f"(c3)
        : "r"(a0), "r"(a1), "r"(a2), "r"(a3), "r"(b0), "r"(b1));
}

__global__ __launch_bounds__(128) void attn_tf32_kernel()
{
    extern __shared__ uint32_t smu[];
    uint32_t* Ks = smu;
    uint32_t* Vs = smu + 64 * KS_STRIDE;
    uint32_t* Ps = smu + 64 * KS_STRIDE + 64 * VS_STRIDE;

    const int qb = blockIdx.x, h = blockIdx.y, b = blockIdx.z;
    const int q0 = qb * 64;
    const int tid = threadIdx.x;
    const int w  = tid >> 5;
    const int l  = tid & 31;
    const int g  = l >> 2;
    const int tg = l & 3;

    const float* Qg = g_q + ((size_t)(b * SEQ + q0)) * D_MODEL + h * DKH;
    const float* Kg = g_k + ((size_t)b * SEQ) * D_MODEL + h * DKH;
    const float* Vg = g_v + ((size_t)b * SEQ) * D_MODEL + h * DKH;

    uint32_t qa[8][4];
    {
        const float* r0 = Qg + (size_t)(16 * w + g) * D_MODEL;
        const float* r1 = Qg + (size_t)(16 * w + g + 8) * D_MODEL;
#pragma unroll
        for (int kc = 0; kc < 8; kc++) {
            qa[kc][0] = f2tf(r0[8 * kc + tg]);
            qa[kc][1] = f2tf(r1[8 * kc + tg]);
            qa[kc][2] = f2tf(r0[8 * kc + tg + 4]);
            qa[kc][3] = f2tf(r1[8 * kc + tg + 4]);
        }
    }

    float o[8][4];
#pragma unroll
    for (int dc = 0; dc < 8; dc++)
#pragma unroll
        for (int j = 0; j < 4; j++) o[dc][j] = 0.0f;
    float m0 = -1e30f, m1 = -1e30f, l0 = 0.0f, l1 = 0.0f;

    for (int kb = 0; kb <= qb; kb++) {
        const int k0 = kb * 64;
        __syncthreads();
#pragma unroll
        for (int i = 0; i < 8; i++) {
            int idx = tid + 128 * i;
            int r   = idx >> 4;
            int c   = (idx & 15) * 4;
            float4 kv = *(const float4*)(Kg + (size_t)(k0 + r) * D_MODEL + c);
            float4 vv = *(const float4*)(Vg + (size_t)(k0 + r) * D_MODEL + c);
            uint4 kt = make_uint4(f2tf(kv.x), f2tf(kv.y), f2tf(kv.z), f2tf(kv.w));
            uint4 vt = make_uint4(f2tf(vv.x), f2tf(vv.y), f2tf(vv.z), f2tf(vv.w));
            *(uint4*)&Ks[r * KS_STRIDE + c] = kt;
            *(uint4*)&Vs[r * VS_STRIDE + c] = vt;
        }
        __syncthreads();

        float s[8][4];
#pragma unroll
        for (int nc = 0; nc < 8; nc++)
#pragma unroll
            for (int j = 0; j < 4; j++) s[nc][j] = 0.0f;

#pragma unroll
        for (int nc = 0; nc < 8; nc++) {
            const uint32_t* krow = &Ks[(8 * nc + g) * KS_STRIDE];
#pragma unroll
            for (int kc = 0; kc < 8; kc++) {
                uint32_t b0 = krow[8 * kc + tg];
                uint32_t b1 = krow[8 * kc + tg + 4];
                mma_tf32(s[nc][0], s[nc][1], s[nc][2], s[nc][3],
                         qa[kc][0], qa[kc][1], qa[kc][2], qa[kc][3], b0, b1);
            }
        }

#pragma unroll
        for (int nc = 0; nc < 8; nc++)
#pragma unroll
            for (int j = 0; j < 4; j++) s[nc][j] *= 0.125f;

        if (kb == qb) {
            const int r0 = 16 * w + g, r1 = r0 + 8;
#pragma unroll
            for (int nc = 0; nc < 8; nc++) {
                int c0 = 8 * nc + 2 * tg, c1 = c0 + 1;
                if (c0 > r0) s[nc][0] = -1e30f;
                if (c1 > r0) s[nc][1] = -1e30f;
                if (c0 > r1) s[nc][2] = -1e30f;
                if (c1 > r1) s[nc][3] = -1e30f;
            }
        }

        float rm0 = -1e30f, rm1 = -1e30f;
#pragma unroll
        for (int nc = 0; nc < 8; nc++) {
            rm0 = fmaxf(rm0, fmaxf(s[nc][0], s[nc][1]));
            rm1 = fmaxf(rm1, fmaxf(s[nc][2], s[nc][3]));
        }
        rm0 = fmaxf(rm0, __shfl_xor_sync(0xffffffffu, rm0, 1));
        rm0 = fmaxf(rm0, __shfl_xor_sync(0xffffffffu, rm0, 2));
        rm1 = fmaxf(rm1, __shfl_xor_sync(0xffffffffu, rm1, 1));
        rm1 = fmaxf(rm1, __shfl_xor_sync(0xffffffffu, rm1, 2));

        float mn0 = fmaxf(m0, rm0), mn1 = fmaxf(m1, rm1);
        float al0 = __expf(m0 - mn0), al1 = __expf(m1 - mn1);
        m0 = mn0; m1 = mn1;

        float rs0 = 0.0f, rs1 = 0.0f;
#pragma unroll
        for (int nc = 0; nc < 8; nc++) {
            float p0 = __expf(s[nc][0] - mn0);
            float p1 = __expf(s[nc][1] - mn0);
            float p2 = __expf(s[nc][2] - mn1);
            float p3 = __expf(s[nc][3] - mn1);
            s[nc][0] = p0; s[nc][1] = p1; s[nc][2] = p2; s[nc][3] = p3;
            rs0 += p0 + p1; rs1 += p2 + p3;
        }
        rs0 += __shfl_xor_sync(0xffffffffu, rs0, 1);
        rs0 += __shfl_xor_sync(0xffffffffu, rs0, 2);
        rs1 += __shfl_xor_sync(0xffffffffu, rs1, 1);
        rs1 += __shfl_xor_sync(0xffffffffu, rs1, 2);
        l0 = l0 * al0 + rs0;
        l1 = l1 * al1 + rs1;

#pragma unroll
        for (int dc = 0; dc < 8; dc++) {
            o[dc][0] *= al0; o[dc][1] *= al0;
            o[dc][2] *= al1; o[dc][3] *= al1;
        }

        {
            const int r0 = 16 * w + g, r1 = r0 + 8;
#pragma unroll
            for (int nc = 0; nc < 8; nc++) {
                uint2 p01 = make_uint2(f2tf(s[nc][0]), f2tf(s[nc][1]));
                uint2 p23 = make_uint2(f2tf(s[nc][2]), f2tf(s[nc][3]));
                *(uint2*)&Ps[r0 * PS_STRIDE + 8 * nc + 2 * tg] = p01;
                *(uint2*)&Ps[r1 * PS_STRIDE + 8 * nc + 2 * tg] = p23;
            }
        }
        __syncwarp();

        uint32_t pa[8][4];
        {
            const uint32_t* p0 = &Ps[(16 * w + g) * PS_STRIDE];
            const uint32_t* p1 = &Ps[(16 * w + g + 8) * PS_STRIDE];
#pragma unroll
            for (int nc = 0; nc < 8; nc++) {
                pa[nc][0] = p0[8 * nc + tg];
                pa[nc][1] = p1[8 * nc + tg];
                pa[nc][2] = p0[8 * nc + tg + 4];
                pa[nc][3] = p1[8 * nc + tg + 4];
            }
        }

#pragma unroll
        for (int dc = 0; dc < 8; dc++) {
#pragma unroll
            for (int nc = 0; nc < 8; nc++) {
                uint32_t b0 = Vs[(8 * nc + tg) * VS_STRIDE + 8 * dc + g];
                uint32_t b1 = Vs[(8 * nc + tg + 4) * VS_STRIDE + 8 * dc + g];
                mma_tf32(o[dc][0], o[dc][1], o[dc][2], o[dc][3],
                         pa[nc][0], pa[nc][1], pa[nc][2], pa[nc][3], b0, b1);
            }
        }
    }

    float* Og = g_ctx + ((size_t)(b * SEQ + q0)) * D_MODEL + h * DKH;
    float il0 = 1.0f / l0, il1 = 1.0f / l1;
    float* w0 = Og + (size_t)(16 * w + g) * D_MODEL;
    float* w1 = Og + (size_t)(16 * w + g + 8) * D_MODEL;
#pragma unroll
    for (int dc = 0; dc < 8; dc++) {
        *(float2*)(w0 + 8 * dc + 2 * tg) = make_float2(o[dc][0] * il0, o[dc][1] * il0);
        *(float2*)(w1 + 8 * dc + 2 * tg) = make_float2(o[dc][2] * il1, o[dc][3] * il1);
    }
}

// ---------------- launch ---------------------------------------------------
extern "C" void kernel_launch(void* const* d_in, const int* in_sizes, int n_in,
                              void* d_out, int out_size)
{
    const float*      X   = (const float*)d_in[0];
    const int*        pos = (const int*)d_in[1];
    const float*      Wq  = (const float*)d_in[2];
    const float*      Wk  = (const float*)d_in[3];
    const float*      Wv  = (const float*)d_in[4];
    const float*      Wo  = (const float*)d_in[5];
    float*            out = (float*)d_out;

    float *dq, *dk, *dv, *dctx;
    cudaGetSymbolAddress((void**)&dq,   g_q);
    cudaGetSymbolAddress((void**)&dk,   g_k);
    cudaGetSymbolAddress((void**)&dv,   g_v);
    cudaGetSymbolAddress((void**)&dctx, g_ctx);

    // RoPE table (transcendentals once)
    rope_table_kernel<<<(SEQ * 32 + 255) / 256, 256>>>(pos);

    // QKV projections (fp16 tensor cores, fp32 accumulate)
    dim3 gqkv(D_MODEL / 128, MT / 128, 3);
    gemm_f16_kernel<<<gqkv, 256>>>(X, Wq, Wk, Wv, dq, dk, dv);

    // RoPE on Q and K from the table
    dim3 gr((unsigned)(((size_t)MT * (D_MODEL / 4) + 255) / 256), 2, 1);
    rope_apply_kernel<<<gr, 256>>>();

    // causal attention (tf32 tensor cores)
    cudaFuncSetAttribute(attn_tf32_kernel, cudaFuncAttributeMaxDynamicSharedMemorySize, ATTN_SMEM_B);
    dim3 ga(SEQ / 64, NHEADS, BATCH);
    attn_tf32_kernel<<<ga, 128, ATTN_SMEM_B>>>();

    // output projection (fp16 tensor cores)
    dim3 go(D_MODEL / 128, MT / 128, 1);
    gemm_f16_kernel<<<go, 256>>>(dctx, Wo, Wo, Wo, out, out, out);
}

// round 17
// speedup vs baseline: 1.6280x; 1.1336x over previous
#include <cuda_runtime.h>
#include <cuda_fp16.h>
#include <math.h>
#include <stdint.h>

#define D_MODEL 1024
#define NHEADS  16
#define DKH     64
#define BATCH   4
#define SEQ     2048
#define MT      (BATCH*SEQ)   // 8192 rows

// ---------------- scratch (device globals; no cudaMalloc allowed) ----------
__device__ float g_q[(size_t)MT * D_MODEL];
__device__ float g_k[(size_t)MT * D_MODEL];
__device__ float g_v[(size_t)MT * D_MODEL];
__device__ float g_ctx[(size_t)MT * D_MODEL];
__device__ uint32_t g_vt[(size_t)BATCH * NHEADS * DKH * (SEQ / 2)]; // [b][h][d][s-pair] half2
__device__ float2 g_rope[(size_t)SEQ * 32];   // [s][k] -> (cos, sin)

// ---------------- helpers ---------------------------------------------------
__device__ __forceinline__ int swz(int r) { return (r & 3) ^ ((r >> 2) & 3); }

__device__ __forceinline__ uint32_t packh2(float lo, float hi) {
    __half2 h = __floats2half2_rn(lo, hi);   // .x = lo bits[0:16)
    return *(uint32_t*)&h;
}

__device__ __forceinline__ void mma_f16(
    float* c, uint32_t a0, uint32_t a1, uint32_t a2, uint32_t a3,
    uint32_t b0, uint32_t b1)
{
    asm volatile(
        "mma.sync.aligned.m16n8k16.row.col.f32.f16.f16.f32 "
        "{%0,%1,%2,%3},{%4,%5,%6,%7},{%8,%9},{%0,%1,%2,%3};"
        : "+f"(c[0]), "+f"(c[1]), "+f"(c[2]), "+f"(c[3])
        : "r"(a0), "r"(a1), "r"(a2), "r"(a3), "r"(b0), "r"(b1));
}

// ---------------- RoPE cos/sin table ----------------------------------------
__global__ void rope_table_kernel(const int* __restrict__ pos32)
{
    int idx = blockIdx.x * 256 + threadIdx.x;
    if (idx >= SEQ * 32) return;
    int s = idx >> 5;
    int k = idx & 31;
    const bool is64 = (pos32[1] == 0 && pos32[2] == 1);
    long long pv = is64 ? ((const long long*)pos32)[s] : (long long)pos32[s];
    float p   = (float)pv;
    float inv = powf(10000.0f, -(float)k * (1.0f / 32.0f));
    float sn, cs;
    sincosf(p * inv, &sn, &cs);
    g_rope[idx] = make_float2(cs, sn);
}

// ---------------- RoPE apply (table-based, float4 = 2 pairs / thread) -------
__global__ void rope_apply_kernel()
{
    const size_t QUADS = (size_t)MT * (D_MODEL / 4);
    size_t idx = (size_t)blockIdx.x * blockDim.x + threadIdx.x;
    if (idx >= QUADS) return;
    float* X = (blockIdx.y == 0) ? g_q : g_k;

    const int m = (int)(idx >> 8);
    const int c4 = (int)(idx & 255);
    const int col = c4 * 4;
    const int k0 = (col & 63) >> 1;
    const int s  = m & (SEQ - 1);

    float2 cs0 = g_rope[s * 32 + k0];
    float2 cs1 = g_rope[s * 32 + k0 + 1];

    float4 v = *(float4*)(X + (size_t)m * D_MODEL + col);
    float4 r;
    r.x = cs0.x * v.x - cs0.y * v.y;
    r.y = cs0.y * v.x + cs0.x * v.y;
    r.z = cs1.x * v.z - cs1.y * v.w;
    r.w = cs1.y * v.z + cs1.x * v.w;
    *(float4*)(X + (size_t)m * D_MODEL + col) = r;
}

// ---------------- V transpose: g_v -> g_vt (half2 pairs along s) ------------
// g_vt[(b*H+h)*64+d][p] = half2{ V[b][2p][h*64+d], V[b][2p+1][h*64+d] }
__global__ __launch_bounds__(128) void vtrans_kernel()
{
    __shared__ float sf[64 * 65];
    const int tid = threadIdx.x;
    const int sb = blockIdx.x, h = blockIdx.y, b = blockIdx.z;
    const float* Vg = g_v + ((size_t)(b * SEQ + sb * 64)) * D_MODEL + h * DKH;

#pragma unroll
    for (int i = 0; i < 8; i++) {
        int idx = tid + 128 * i;
        int r = idx >> 4, c = (idx & 15) * 4;
        float4 v = *(const float4*)(Vg + (size_t)r * D_MODEL + c);
        // scalar stores: stride 65 breaks float4 smem alignment (R15 crash)
        sf[r * 65 + c + 0] = v.x;
        sf[r * 65 + c + 1] = v.y;
        sf[r * 65 + c + 2] = v.z;
        sf[r * 65 + c + 3] = v.w;
    }
    __syncthreads();

    uint32_t* out = g_vt + ((size_t)((b * NHEADS + h) * DKH)) * (SEQ / 2) + sb * 32;
#pragma unroll
    for (int i = 0; i < 8; i++) {
        int idx = tid + 128 * i;
        int d = idx >> 4, pq = (idx & 15) * 2;
        uint32_t p0 = packh2(sf[(2 * pq + 0) * 65 + d], sf[(2 * pq + 1) * 65 + d]);
        uint32_t p1 = packh2(sf[(2 * pq + 2) * 65 + d], sf[(2 * pq + 3) * 65 + d]);
        *(uint2*)(out + (size_t)d * (SEQ / 2) + pq) = make_uint2(p0, p1);
    }
}

// ---------------- fp16 GEMM: C[m,n] = sum_d A[m,d] * W[n,d]  (NT) -----------
// Unchanged from R14 (passing).
__global__ __launch_bounds__(256, 2) void gemm_f16_kernel(
    const float* __restrict__ A,
    const float* __restrict__ W0, const float* __restrict__ W1, const float* __restrict__ W2,
    float* __restrict__ C0, float* __restrict__ C1, float* __restrict__ C2)
{
    const float* W; float* C;
    if (blockIdx.z == 0)      { W = W0; C = C0; }
    else if (blockIdx.z == 1) { W = W1; C = C1; }
    else                      { W = W2; C = C2; }

    __shared__ uint32_t As[2][128 * 8];
    __shared__ uint32_t Ws[2][128 * 8];

    const int tid = threadIdx.x;
    const int w  = tid >> 5;
    const int l  = tid & 31;
    const int g  = l >> 2;
    const int tg = l & 3;
    const int m0 = blockIdx.y * 128;
    const int n0 = blockIdx.x * 128;
    const int wm = (w & 3) * 32;
    const int wn = (w >> 2) * 64;

    const int lr = tid & 127;
    const bool isA = (tid < 128);
    const float* G = isA ? (A + (size_t)(m0 + lr) * D_MODEL)
                         : (W + (size_t)(n0 + lr) * D_MODEL);
    const int srx = swz(lr);
    const int sq0 = 2 * (0 ^ srx), sq1 = 2 * (1 ^ srx);
    const int sq2 = 2 * (2 ^ srx), sq3 = 2 * (3 ^ srx);

    int aoff[2][2], boff[8];
#pragma unroll
    for (int mi = 0; mi < 2; mi++)
#pragma unroll
        for (int hf = 0; hf < 2; hf++) {
            int row = wm + 16 * mi + 8 * hf + g;
            aoff[mi][hf] = row * 8 + 2 * (tg ^ swz(row));
        }
#pragma unroll
    for (int ni = 0; ni < 8; ni++) {
        int row = wn + 8 * ni + g;
        boff[ni] = row * 8 + 2 * (tg ^ swz(row));
    }

    float acc[2][8][4];
#pragma unroll
    for (int mi = 0; mi < 2; mi++)
#pragma unroll
        for (int ni = 0; ni < 8; ni++)
#pragma unroll
            for (int j = 0; j < 4; j++) acc[mi][ni][j] = 0.0f;

    float4 v0 = *(const float4*)(G + 0);
    float4 v1 = *(const float4*)(G + 4);
    float4 v2 = *(const float4*)(G + 8);
    float4 v3 = *(const float4*)(G + 12);

#pragma unroll 1
    for (int t = 0; t < D_MODEL / 16; t++) {
        const int buf = t & 1;
        {
            uint32_t* Sb = (isA ? As[buf] : Ws[buf]) + lr * 8;
            uint32_t pk0 = packh2(v0.x, v0.y);
            uint32_t pk1 = packh2(v0.z, v0.w);
            uint32_t pk2 = packh2(v1.x, v1.y);
            uint32_t pk3 = packh2(v1.z, v1.w);
            uint32_t pk4 = packh2(v2.x, v2.y);
            uint32_t pk5 = packh2(v2.z, v2.w);
            uint32_t pk6 = packh2(v3.x, v3.y);
            uint32_t pk7 = packh2(v3.z, v3.w);
            *(uint2*)&Sb[sq0] = make_uint2(pk0, pk4);
            *(uint2*)&Sb[sq1] = make_uint2(pk1, pk5);
            *(uint2*)&Sb[sq2] = make_uint2(pk2, pk6);
            *(uint2*)&Sb[sq3] = make_uint2(pk3, pk7);
        }
        __syncthreads();

        if (t + 1 < D_MODEL / 16) {
            const float* Gn = G + (t + 1) * 16;
            v0 = *(const float4*)(Gn + 0);
            v1 = *(const float4*)(Gn + 4);
            v2 = *(const float4*)(Gn + 8);
            v3 = *(const float4*)(Gn + 12);
        }

        {
            const uint32_t* Ab = As[buf];
            const uint32_t* Wb = Ws[buf];
            uint2 af[2][2], bf[8];
#pragma unroll
            for (int mi = 0; mi < 2; mi++) {
                af[mi][0] = *(const uint2*)&Ab[aoff[mi][0]];
                af[mi][1] = *(const uint2*)&Ab[aoff[mi][1]];
            }
#pragma unroll
            for (int ni = 0; ni < 8; ni++)
                bf[ni] = *(const uint2*)&Wb[boff[ni]];

#pragma unroll
            for (int mi = 0; mi < 2; mi++)
#pragma unroll
                for (int ni = 0; ni < 8; ni++)
                    mma_f16(acc[mi][ni],
                            af[mi][0].x, af[mi][1].x, af[mi][0].y, af[mi][1].y,
                            bf[ni].x, bf[ni].y);
        }
    }

#pragma unroll
    for (int mi = 0; mi < 2; mi++) {
        const size_t row0 = (size_t)(m0 + wm + 16 * mi + g);
        const size_t row1 = row0 + 8;
#pragma unroll
        for (int ni = 0; ni < 8; ni++) {
            const int col = n0 + wn + 8 * ni + 2 * tg;
            *(float2*)(C + row0 * D_MODEL + col) = make_float2(acc[mi][ni][0], acc[mi][ni][1]);
            *(float2*)(C + row1 * D_MODEL + col) = make_float2(acc[mi][ni][2], acc[mi][ni][3]);
        }
    }
}

// ---------------- fp16 flash attention --------------------------------------
// All smem in half2-pair layout, stride 36 words (4g+tg bijective mod 32).
// Ks[row][pair k], Vw[d][pair k] (from g_vt), Pw[row][pair col].
#define KSP 36
#define ATTN_SMEM_W (3 * 64 * KSP)
#define ATTN_SMEM_B (ATTN_SMEM_W * 4)

__global__ __launch_bounds__(128) void attn_f16_kernel()
{
    extern __shared__ uint32_t smu[];
    uint32_t* Ks = smu;                 // [64][36]
    uint32_t* Vw = smu + 64 * KSP;      // [64][36]
    uint32_t* Pw = smu + 2 * 64 * KSP;  // [64][36]

    const int qb = blockIdx.x, h = blockIdx.y, b = blockIdx.z;
    const int q0 = qb * 64;
    const int tid = threadIdx.x;
    const int w  = tid >> 5;
    const int l  = tid & 31;
    const int g  = l >> 2;
    const int tg = l & 3;
    const int r0 = 16 * w + g;
    const int r1 = r0 + 8;

    const float* Qg = g_q + ((size_t)(b * SEQ + q0)) * D_MODEL + h * DKH;
    const float* Kg = g_k + ((size_t)b * SEQ) * D_MODEL + h * DKH;
    const uint32_t* Vtg = g_vt + ((size_t)((b * NHEADS + h) * DKH)) * (SEQ / 2);

    // Q fragments (fp16 pairs), 4 k-chunks of 16
    uint32_t qa[4][4];
    {
        const float* q0p = Qg + (size_t)r0 * D_MODEL;
        const float* q1p = Qg + (size_t)r1 * D_MODEL;
#pragma unroll
        for (int kc = 0; kc < 4; kc++) {
            float2 a00 = *(const float2*)(q0p + 16 * kc + 2 * tg);
            float2 a10 = *(const float2*)(q1p + 16 * kc + 2 * tg);
            float2 a01 = *(const float2*)(q0p + 16 * kc + 8 + 2 * tg);
            float2 a11 = *(const float2*)(q1p + 16 * kc + 8 + 2 * tg);
            qa[kc][0] = packh2(a00.x, a00.y);
            qa[kc][1] = packh2(a10.x, a10.y);
            qa[kc][2] = packh2(a01.x, a01.y);
            qa[kc][3] = packh2(a11.x, a11.y);
        }
    }

    float o[8][4];
#pragma unroll
    for (int dc = 0; dc < 8; dc++)
#pragma unroll
        for (int j = 0; j < 4; j++) o[dc][j] = 0.0f;
    float m0 = -1e30f, m1 = -1e30f, l0 = 0.0f, l1 = 0.0f;

    for (int kb = 0; kb <= qb; kb++) {
        const int k0 = kb * 64;
        __syncthreads();
        // K: pack pairs along k; V: pre-packed from g_vt (coalesced uint2)
#pragma unroll
        for (int i = 0; i < 8; i++) {
            int idx = tid + 128 * i;
            int r   = idx >> 4;
            int c   = (idx & 15) * 4;        // k element base (K)
            int pq  = (idx & 15) * 2;        // pair base (V)
            float4 kv = *(const float4*)(Kg + (size_t)(k0 + r) * D_MODEL + c);
            *(uint2*)&Ks[r * KSP + (c >> 1)] =
                make_uint2(packh2(kv.x, kv.y), packh2(kv.z, kv.w));
            uint2 vv = *(const uint2*)(Vtg + (size_t)r * (SEQ / 2) + kb * 32 + pq);
            *(uint2*)&Vw[r * KSP + pq] = vv;
        }
        __syncthreads();

        // ---- S = Q K^T ----
        float s[8][4];
#pragma unroll
        for (int nc = 0; nc < 8; nc++)
#pragma unroll
            for (int j = 0; j < 4; j++) s[nc][j] = 0.0f;

#pragma unroll
        for (int nc = 0; nc < 8; nc++) {
            const uint32_t* krow = &Ks[(8 * nc + g) * KSP];
#pragma unroll
            for (int kc = 0; kc < 4; kc++) {
                uint32_t b0 = krow[8 * kc + tg];
                uint32_t b1 = krow[8 * kc + tg + 4];
                mma_f16(s[nc], qa[kc][0], qa[kc][1], qa[kc][2], qa[kc][3], b0, b1);
            }
        }

#pragma unroll
        for (int nc = 0; nc < 8; nc++)
#pragma unroll
            for (int j = 0; j < 4; j++) s[nc][j] *= 0.125f;

        if (kb == qb) {
#pragma unroll
            for (int nc = 0; nc < 8; nc++) {
                int c0 = 8 * nc + 2 * tg, c1 = c0 + 1;
                if (c0 > r0) s[nc][0] = -1e30f;
                if (c1 > r0) s[nc][1] = -1e30f;
                if (c0 > r1) s[nc][2] = -1e30f;
                if (c1 > r1) s[nc][3] = -1e30f;
            }
        }

        // ---- online softmax ----
        float rm0 = -1e30f, rm1 = -1e30f;
#pragma unroll
        for (int nc = 0; nc < 8; nc++) {
            rm0 = fmaxf(rm0, fmaxf(s[nc][0], s[nc][1]));
            rm1 = fmaxf(rm1, fmaxf(s[nc][2], s[nc][3]));
        }
        rm0 = fmaxf(rm0, __shfl_xor_sync(0xffffffffu, rm0, 1));
        rm0 = fmaxf(rm0, __shfl_xor_sync(0xffffffffu, rm0, 2));
        rm1 = fmaxf(rm1, __shfl_xor_sync(0xffffffffu, rm1, 1));
        rm1 = fmaxf(rm1, __shfl_xor_sync(0xffffffffu, rm1, 2));

        float mn0 = fmaxf(m0, rm0), mn1 = fmaxf(m1, rm1);
        float al0 = __expf(m0 - mn0), al1 = __expf(m1 - mn1);
        m0 = mn0; m1 = mn1;

        float rs0 = 0.0f, rs1 = 0.0f;
#pragma unroll
        for (int nc = 0; nc < 8; nc++) {
            float p0 = __expf(s[nc][0] - mn0);
            float p1 = __expf(s[nc][1] - mn0);
            float p2 = __expf(s[nc][2] - mn1);
            float p3 = __expf(s[nc][3] - mn1);
            s[nc][0] = p0; s[nc][1] = p1; s[nc][2] = p2; s[nc][3] = p3;
            rs0 += p0 + p1; rs1 += p2 + p3;
        }
        rs0 += __shfl_xor_sync(0xffffffffu, rs0, 1);
        rs0 += __shfl_xor_sync(0xffffffffu, rs0, 2);
        rs1 += __shfl_xor_sync(0xffffffffu, rs1, 1);
        rs1 += __shfl_xor_sync(0xffffffffu, rs1, 2);
        l0 = l0 * al0 + rs0;
        l1 = l1 * al1 + rs1;

#pragma unroll
        for (int dc = 0; dc < 8; dc++) {
            o[dc][0] *= al0; o[dc][1] *= al0;
            o[dc][2] *= al1; o[dc][3] *= al1;
        }

        // ---- P -> smem as fp16 pairs (warp-private rows) ----
#pragma unroll
        for (int nc = 0; nc < 8; nc++) {
            Pw[r0 * KSP + 4 * nc + tg] = packh2(s[nc][0], s[nc][1]);
            Pw[r1 * KSP + 4 * nc + tg] = packh2(s[nc][2], s[nc][3]);
        }
        __syncwarp();

        uint32_t pa[4][4];
#pragma unroll
        for (int kc = 0; kc < 4; kc++) {
            pa[kc][0] = Pw[r0 * KSP + 8 * kc + tg];
            pa[kc][1] = Pw[r1 * KSP + 8 * kc + tg];
            pa[kc][2] = Pw[r0 * KSP + 8 * kc + tg + 4];
            pa[kc][3] = Pw[r1 * KSP + 8 * kc + tg + 4];
        }

        // ---- O += P V ----
#pragma unroll
        for (int dc = 0; dc < 8; dc++) {
            const uint32_t* vrow = &Vw[(8 * dc + g) * KSP];
#pragma unroll
            for (int kc = 0; kc < 4; kc++) {
                uint32_t b0 = vrow[8 * kc + tg];
                uint32_t b1 = vrow[8 * kc + tg + 4];
                mma_f16(o[dc], pa[kc][0], pa[kc][1], pa[kc][2], pa[kc][3], b0, b1);
            }
        }
    }

    float* Og = g_ctx + ((size_t)(b * SEQ + q0)) * D_MODEL + h * DKH;
    float il0 = 1.0f / l0, il1 = 1.0f / l1;
    float* w0 = Og + (size_t)r0 * D_MODEL;
    float* w1 = Og + (size_t)r1 * D_MODEL;
#pragma unroll
    for (int dc = 0; dc < 8; dc++) {
        *(float2*)(w0 + 8 * dc + 2 * tg) = make_float2(o[dc][0] * il0, o[dc][1] * il0);
        *(float2*)(w1 + 8 * dc + 2 * tg) = make_float2(o[dc][2] * il1, o[dc][3] * il1);
    }
}

// ---------------- launch ---------------------------------------------------
extern "C" void kernel_launch(void* const* d_in, const int* in_sizes, int n_in,
                              void* d_out, int out_size)
{
    const float*      X   = (const float*)d_in[0];
    const int*        pos = (const int*)d_in[1];
    const float*      Wq  = (const float*)d_in[2];
    const float*      Wk  = (const float*)d_in[3];
    const float*      Wv  = (const float*)d_in[4];
    const float*      Wo  = (const float*)d_in[5];
    float*            out = (float*)d_out;

    float *dq, *dk, *dv, *dctx;
    cudaGetSymbolAddress((void**)&dq,   g_q);
    cudaGetSymbolAddress((void**)&dk,   g_k);
    cudaGetSymbolAddress((void**)&dv,   g_v);
    cudaGetSymbolAddress((void**)&dctx, g_ctx);

    // RoPE table
    rope_table_kernel<<<(SEQ * 32 + 255) / 256, 256>>>(pos);

    // QKV projections (fp16 tensor cores)
    dim3 gqkv(D_MODEL / 128, MT / 128, 3);
    gemm_f16_kernel<<<gqkv, 256>>>(X, Wq, Wk, Wv, dq, dk, dv);

    // RoPE on Q and K
    dim3 gr((unsigned)(((size_t)MT * (D_MODEL / 4) + 255) / 256), 2, 1);
    rope_apply_kernel<<<gr, 256>>>();

    // V transpose into packed half2 pairs
    dim3 gv(SEQ / 64, NHEADS, BATCH);
    vtrans_kernel<<<gv, 128>>>();

    // causal attention (fp16 tensor cores)
    cudaFuncSetAttribute(attn_f16_kernel, cudaFuncAttributeMaxDynamicSharedMemorySize, ATTN_SMEM_B);
    dim3 ga(SEQ / 64, NHEADS, BATCH);
    attn_f16_kernel<<<ga, 128, ATTN_SMEM_B>>>();

    // output projection (fp16 tensor cores)
    dim3 go(D_MODEL / 128, MT / 128, 1);
    gemm_f16_kernel<<<go, 256>>>(dctx, Wo, Wo, Wo, out, out, out);
}